// round 7
// baseline (speedup 1.0000x reference)
#include <cuda_runtime.h>
#include <cstdint>

#define BB   8
#define CC   64
#define NP   12800
#define NS   3200
#define KNN  16
#define HWD  19200
#define NOUT 22400            // HWD + NS
#define NT   25600            // BB * NS (flattened point axis)

#define RSW   132             // W smem row stride (128 + 4 pad), 16B-aligned
#define RSX   260             // X smem row stride (256 + 4 pad), 16B-aligned
#define SMEM2 ((64 * RSW + 64 * RSX) * 4)   // 100,352 B

// ---------------- scratch (device globals; no allocation) ----------------
__device__ __align__(16) float g_pT     [(size_t)BB * NP * CC];   // p  point-major [B,NP,64]
__device__ __align__(16) float g_rgbT   [(size_t)BB * HWD * CC];  // rgb point-major [B,HW,64]
__device__ __align__(16) float g_pemb_cm[(size_t)CC * NT];        // p_emb0 channel-major [64][NT]
__device__ __align__(16) float g_r2pg_cm[(size_t)CC * NT];        // rgb gather+max cm    [64][NT]
__device__ __align__(16) float g_qT     [(size_t)NT * CC];        // q point-major [NT][64]
__device__ __align__(16) float g_r2pp_cm[(size_t)CC * NT];        // r2p_pre cm    [64][NT]

// ---------------- packed fp32x2 helpers ----------------
__device__ __forceinline__ unsigned long long ffma2(unsigned long long a,
                                                    unsigned long long b,
                                                    unsigned long long c) {
    unsigned long long d;
    asm("fma.rn.f32x2 %0, %1, %2, %3;" : "=l"(d) : "l"(a), "l"(b), "l"(c));
    return d;
}
__device__ __forceinline__ float2 u2f(unsigned long long u) {
    float2 f;
    asm("mov.b64 {%0, %1}, %2;" : "=f"(f.x), "=f"(f.y) : "l"(u));
    return f;
}

// ---------------- transpose [B,64,N] -> [B,N,64] ----------------
__device__ __forceinline__ void transpose_body(const float* __restrict__ src,
                                               float* __restrict__ dst, int N, int n0) {
    __shared__ __align__(16) float s[32][33];
    const int b  = blockIdx.z;
    const int c0 = blockIdx.y * 32;
    const int tx = threadIdx.x, ty = threadIdx.y;
    const float* sp = src + ((size_t)b * CC + c0) * N + n0;
#pragma unroll
    for (int i = 0; i < 4; i++)
        s[ty + 8 * i][tx] = sp[(size_t)(ty + 8 * i) * N + tx];
    __syncthreads();
    float* dp = dst + ((size_t)b * N + n0) * CC + c0;
#pragma unroll
    for (int i = 0; i < 4; i++)
        dp[(size_t)(ty + 8 * i) * CC + tx] = s[tx][ty + 8 * i];
}

__global__ void __launch_bounds__(256, 2)
k_transpose_all(const float* __restrict__ p, const float* __restrict__ rgb) {
    if (blockIdx.x < NP / 32) transpose_body(p,   g_pT,   NP,  blockIdx.x * 32);
    else                      transpose_body(rgb, g_rgbT, HWD, (blockIdx.x - NP / 32) * 32);
}

// ---------------- gather + maxpool -> channel-major output ----------------
// Block = 256 threads = 8 warps; handles 64 flattened points; smem transpose; cm write.
__device__ __forceinline__ void gather_cm_body(const float* __restrict__ srcT,
                                               const int* __restrict__ idx,
                                               float* __restrict__ dst_cm,
                                               int Nsrc, int bx) {
    __shared__ __align__(16) float sg[64][65];
    const int t    = threadIdx.x;
    const int wid  = t >> 5;
    const int lane = t & 31;
    const int g0   = bx * 64;

#pragma unroll
    for (int r = 0; r < 8; r++) {
        const int pl = wid * 8 + r;          // local point 0..63
        const int g  = g0 + pl;              // flattened point
        const int b  = g / NS;
        const int* ip = idx + (size_t)g * KNN;
        int id[KNN];
#pragma unroll
        for (int k = 0; k < KNN; k++) id[k] = __ldg(ip + k);
        float2 v[KNN];
#pragma unroll
        for (int k = 0; k < KNN; k++) {
            const float2* rr = (const float2*)(srcT + ((size_t)b * Nsrc + id[k]) * CC);
            v[k] = __ldg(rr + lane);
        }
        float2 acc = v[0];
#pragma unroll
        for (int k = 1; k < KNN; k++) {
            acc.x = fmaxf(acc.x, v[k].x);
            acc.y = fmaxf(acc.y, v[k].y);
        }
        sg[2 * lane][pl]     = acc.x;
        sg[2 * lane + 1][pl] = acc.y;
    }
    __syncthreads();
    // write cm: 64 rows x 64 cols, coalesced float4 per thread
#pragma unroll
    for (int i = 0; i < 4; i++) {
        int f4 = t + 256 * i;                // < 1024
        int c = f4 >> 4, n4 = f4 & 15;
        float4 o = make_float4(sg[c][4 * n4], sg[c][4 * n4 + 1],
                               sg[c][4 * n4 + 2], sg[c][4 * n4 + 3]);
        *(float4*)(dst_cm + (size_t)c * NT + g0 + 4 * n4) = o;
    }
}

__global__ void __launch_bounds__(256, 2)
k_gather_all(const int* __restrict__ pool_idx, const int* __restrict__ r2p_idx) {
    const int half = NT / 64;   // 400
    if (blockIdx.x < half) gather_cm_body(g_pT,   pool_idx, g_pemb_cm, NP,  blockIdx.x);
    else                   gather_cm_body(g_rgbT, r2p_idx,  g_r2pg_cm, HWD, blockIdx.x - half);
}

// ---------------- GEMM tile loaders ----------------
// Wd[c][2o], Wd[c][2o+1] = w[o][c]  (dup pairs so LDS.128 yields packed broadcasts)
__device__ __forceinline__ void load_wd(float* Wd, const float* __restrict__ w,
                                        int stride, int t) {
#pragma unroll
    for (int i = 0; i < 16; i++) {
        int f = t + 256 * i;                 // < 4096
        int o = f >> 6, c = f & 63;
        float v = __ldg(w + (size_t)o * stride + c);
        Wd[c * RSW + 2 * o]     = v;
        Wd[c * RSW + 2 * o + 1] = v;
    }
}
// X tile from channel-major source (row stride Nsrc), 64c x 256n, conflict-free
__device__ __forceinline__ void load_x_cm(float* Xs, const float* __restrict__ x,
                                          int Nsrc, int t) {
#pragma unroll
    for (int i = 0; i < 16; i++) {
        int f4 = t + 256 * i;                // < 4096
        int n4 = f4 & 63, c = f4 >> 6;
        float4 v = *(const float4*)(x + (size_t)c * Nsrc + 4 * n4);
        *(float4*)(Xs + c * RSX + 4 * n4) = v;
    }
}

// ---------------- FFMA2 GEMM core: 64 K-steps, thread tile 4o x 16n ----------------
// o in {2ty,2ty+1,2ty+32,2ty+33}; n groups nb_j = 4tx + 64j, j=0..3 (pairs nb,nb+1 / nb+2,nb+3)
__device__ __forceinline__ void mm64w(const float* Wd, const float* Xs, int tx, int ty,
                                      unsigned long long acc[4][8]) {
#pragma unroll 8
    for (int c = 0; c < 64; c++) {
        const float* wr = Wd + c * RSW;
        const float* xr = Xs + c * RSX;
        ulonglong2 wa = *(const ulonglong2*)(wr + 4 * ty);
        ulonglong2 wb = *(const ulonglong2*)(wr + 4 * ty + 64);
        unsigned long long w[4] = {wa.x, wa.y, wb.x, wb.y};
#pragma unroll
        for (int j = 0; j < 4; j++) {
            ulonglong2 xj = *(const ulonglong2*)(xr + 4 * tx + 64 * j);
#pragma unroll
            for (int i = 0; i < 4; i++) {
                acc[i][2 * j]     = ffma2(w[i], xj.x, acc[i][2 * j]);
                acc[i][2 * j + 1] = ffma2(w[i], xj.y, acc[i][2 * j + 1]);
            }
        }
    }
}

// ---------------- pre kernel: y=0 p2r chain (-> g_qT), y=1 r2p_pre (-> g_r2pp_cm) ----
__global__ void __launch_bounds__(256, 2)
k_pre(const float* __restrict__ w_p2r_pre, const float* __restrict__ s_p2r_pre,
      const float* __restrict__ b_p2r_pre, const float* __restrict__ w_p2r_fuse,
      const float* __restrict__ w_r2p_pre, const float* __restrict__ s_r2p_pre,
      const float* __restrict__ b_r2p_pre) {
    extern __shared__ float sm[];
    float* Wd = sm;
    float* Xs = sm + 64 * RSW;
    const int n0 = blockIdx.x * 256;
    const int t = threadIdx.x, tx = t & 15, ty = t >> 4;
    const int o_[4] = {2 * ty, 2 * ty + 1, 2 * ty + 32, 2 * ty + 33};

    if (blockIdx.y == 0) {
        load_x_cm(Xs, g_pemb_cm + n0, NT, t);
        load_wd(Wd, w_p2r_pre, 64, t);
        __syncthreads();
        unsigned long long acc[4][8] = {};
        mm64w(Wd, Xs, tx, ty, acc);

        float s4[4], b4[4];
#pragma unroll
        for (int i = 0; i < 4; i++) { s4[i] = __ldg(s_p2r_pre + o_[i]); b4[i] = __ldg(b_p2r_pre + o_[i]); }
        __syncthreads();                 // all reads of Xs/Wd done
#pragma unroll
        for (int p = 0; p < 8; p++) {
            int nb = 4 * tx + 64 * (p >> 1) + 2 * (p & 1);
#pragma unroll
            for (int i = 0; i < 4; i++) {
                float2 v = u2f(acc[i][p]);
                v.x = fmaxf(v.x * s4[i] + b4[i], 0.0f);
                v.y = fmaxf(v.y * s4[i] + b4[i], 0.0f);
                *(float2*)(Xs + o_[i] * RSX + nb) = v;
            }
        }
        load_wd(Wd, w_p2r_fuse + 64, 128, t);   // point half of fuse weights
        __syncthreads();

        unsigned long long acc2[4][8] = {};
        mm64w(Wd, Xs, tx, ty, acc2);

#pragma unroll
        for (int p = 0; p < 8; p++) {
            int nb = 4 * tx + 64 * (p >> 1) + 2 * (p & 1);
            size_t ng = (size_t)(n0 + nb);
            float2 a0 = u2f(acc2[0][p]), a1 = u2f(acc2[1][p]);
            float2 a2 = u2f(acc2[2][p]), a3 = u2f(acc2[3][p]);
            *(float2*)(g_qT + ng * CC + 2 * ty)            = make_float2(a0.x, a1.x);
            *(float2*)(g_qT + ng * CC + 2 * ty + 32)       = make_float2(a2.x, a3.x);
            *(float2*)(g_qT + (ng + 1) * CC + 2 * ty)      = make_float2(a0.y, a1.y);
            *(float2*)(g_qT + (ng + 1) * CC + 2 * ty + 32) = make_float2(a2.y, a3.y);
        }
    } else {
        load_x_cm(Xs, g_r2pg_cm + n0, NT, t);
        load_wd(Wd, w_r2p_pre, 64, t);
        __syncthreads();
        unsigned long long acc[4][8] = {};
        mm64w(Wd, Xs, tx, ty, acc);

        float s4[4], b4[4];
#pragma unroll
        for (int i = 0; i < 4; i++) { s4[i] = __ldg(s_r2p_pre + o_[i]); b4[i] = __ldg(b_r2p_pre + o_[i]); }
#pragma unroll
        for (int p = 0; p < 8; p++) {
            int nb = 4 * tx + 64 * (p >> 1) + 2 * (p & 1);
#pragma unroll
            for (int i = 0; i < 4; i++) {
                float2 v = u2f(acc[i][p]);
                v.x = fmaxf(v.x * s4[i] + b4[i], 0.0f);
                v.y = fmaxf(v.y * s4[i] + b4[i], 0.0f);
                *(float2*)(g_r2pp_cm + (size_t)o_[i] * NT + n0 + nb) = v;
            }
        }
    }
}

// ---------------- rgb_out = relu(s*(W_lo@rgb + q[:, p2r_idx]) + b) ----------------
__global__ void __launch_bounds__(256, 2)
k_rgb_out(const float* __restrict__ rgb, const float* __restrict__ w_fuse,
          const float* __restrict__ s, const float* __restrict__ bias,
          const int* __restrict__ p2r_idx, float* __restrict__ out) {
    extern __shared__ float sm[];
    float* Wd = sm;
    float* Xs = sm + 64 * RSW;
    const int b = blockIdx.y, n0 = blockIdx.x * 256;
    const int t = threadIdx.x, tx = t & 15, ty = t >> 4;
    const int o_[4] = {2 * ty, 2 * ty + 1, 2 * ty + 32, 2 * ty + 33};

    load_x_cm(Xs, rgb + (size_t)b * CC * HWD + n0, HWD, t);
    load_wd(Wd, w_fuse, 128, t);
    __syncthreads();
    unsigned long long acc[4][8] = {};
    mm64w(Wd, Xs, tx, ty, acc);

    float s4[4], b4[4];
#pragma unroll
    for (int i = 0; i < 4; i++) { s4[i] = __ldg(s + o_[i]); b4[i] = __ldg(bias + o_[i]); }

    const int* ip = p2r_idx + (size_t)b * HWD + n0;
    const float* qbase = g_qT + (size_t)b * NS * CC;

#pragma unroll
    for (int j = 0; j < 4; j++) {
        int nb = 4 * tx + 64 * j;
        int id4[4];
#pragma unroll
        for (int u = 0; u < 4; u++) id4[u] = __ldg(ip + nb + u);
        float qv[4][4];                        // [n-in-group][i]
#pragma unroll
        for (int u = 0; u < 4; u++) {
            const float* qr = qbase + (size_t)id4[u] * CC;
            float2 qlo = *(const float2*)(qr + 2 * ty);
            float2 qhi = *(const float2*)(qr + 2 * ty + 32);
            qv[u][0] = qlo.x; qv[u][1] = qlo.y; qv[u][2] = qhi.x; qv[u][3] = qhi.y;
        }
#pragma unroll
        for (int i = 0; i < 4; i++) {
            float2 a0 = u2f(acc[i][2 * j]);
            float2 a1 = u2f(acc[i][2 * j + 1]);
            float4 v4 = make_float4(fmaxf((a0.x + qv[0][i]) * s4[i] + b4[i], 0.0f),
                                    fmaxf((a0.y + qv[1][i]) * s4[i] + b4[i], 0.0f),
                                    fmaxf((a1.x + qv[2][i]) * s4[i] + b4[i], 0.0f),
                                    fmaxf((a1.y + qv[3][i]) * s4[i] + b4[i], 0.0f));
            *(float4*)(out + ((size_t)(b * CC + o_[i])) * NOUT + n0 + nb) = v4;
        }
    }
}

// ---------------- p_out = relu(s*(Wf_lo@p_emb0 + Wf_hi@r2p_pre) + b) ----------------
__global__ void __launch_bounds__(256, 2)
k_p_out(const float* __restrict__ w_fuse, const float* __restrict__ s,
        const float* __restrict__ bias, float* __restrict__ out) {
    extern __shared__ float sm[];
    float* Wd = sm;
    float* Xs = sm + 64 * RSW;
    const int n0 = blockIdx.x * 256;
    const int t = threadIdx.x, tx = t & 15, ty = t >> 4;
    const int o_[4] = {2 * ty, 2 * ty + 1, 2 * ty + 32, 2 * ty + 33};

    unsigned long long acc[4][8] = {};

    load_x_cm(Xs, g_pemb_cm + n0, NT, t);
    load_wd(Wd, w_fuse, 128, t);
    __syncthreads();
    mm64w(Wd, Xs, tx, ty, acc);
    __syncthreads();

    load_x_cm(Xs, g_r2pp_cm + n0, NT, t);
    load_wd(Wd, w_fuse + 64, 128, t);
    __syncthreads();
    mm64w(Wd, Xs, tx, ty, acc);

    float s4[4], b4[4];
#pragma unroll
    for (int i = 0; i < 4; i++) { s4[i] = __ldg(s + o_[i]); b4[i] = __ldg(bias + o_[i]); }

#pragma unroll
    for (int j = 0; j < 4; j++) {
        int nb  = 4 * tx + 64 * j;
        int ng  = n0 + nb;
        int bb  = ng / NS;
        int col = ng - bb * NS;
#pragma unroll
        for (int i = 0; i < 4; i++) {
            float2 a0 = u2f(acc[i][2 * j]);
            float2 a1 = u2f(acc[i][2 * j + 1]);
            float4 v4 = make_float4(fmaxf(a0.x * s4[i] + b4[i], 0.0f),
                                    fmaxf(a0.y * s4[i] + b4[i], 0.0f),
                                    fmaxf(a1.x * s4[i] + b4[i], 0.0f),
                                    fmaxf(a1.y * s4[i] + b4[i], 0.0f));
            *(float4*)(out + ((size_t)(bb * CC + o_[i])) * NOUT + HWD + col) = v4;
        }
    }
}

// ---------------- launch ----------------
extern "C" void kernel_launch(void* const* d_in, const int* in_sizes, int n_in,
                              void* d_out, int out_size) {
    const float* rgb_feat   = (const float*)d_in[0];
    const float* p_feat     = (const float*)d_in[1];
    const float* w_p2r_pre  = (const float*)d_in[2];
    const float* s_p2r_pre  = (const float*)d_in[3];
    const float* b_p2r_pre  = (const float*)d_in[4];
    const float* w_p2r_fuse = (const float*)d_in[5];
    const float* s_p2r_fuse = (const float*)d_in[6];
    const float* b_p2r_fuse = (const float*)d_in[7];
    const float* w_r2p_pre  = (const float*)d_in[8];
    const float* s_r2p_pre  = (const float*)d_in[9];
    const float* b_r2p_pre  = (const float*)d_in[10];
    const float* w_r2p_fuse = (const float*)d_in[11];
    const float* s_r2p_fuse = (const float*)d_in[12];
    const float* b_r2p_fuse = (const float*)d_in[13];
    const int*   pool_idx   = (const int*)d_in[14];
    const int*   p2r_idx    = (const int*)d_in[15];
    const int*   r2p_idx    = (const int*)d_in[16];
    float* out = (float*)d_out;

    cudaFuncSetAttribute(k_pre,     cudaFuncAttributeMaxDynamicSharedMemorySize, SMEM2);
    cudaFuncSetAttribute(k_rgb_out, cudaFuncAttributeMaxDynamicSharedMemorySize, SMEM2);
    cudaFuncSetAttribute(k_p_out,   cudaFuncAttributeMaxDynamicSharedMemorySize, SMEM2);

    k_transpose_all<<<dim3(NP / 32 + HWD / 32, 2, BB), dim3(32, 8)>>>(p_feat, rgb_feat);
    k_gather_all<<<2 * (NT / 64), 256>>>(pool_idx, r2p_idx);

    k_pre<<<dim3(NT / 256, 2), 256, SMEM2>>>(w_p2r_pre, s_p2r_pre, b_p2r_pre, w_p2r_fuse,
                                             w_r2p_pre, s_r2p_pre, b_r2p_pre);

    k_rgb_out<<<dim3(HWD / 256, BB), 256, SMEM2>>>(rgb_feat, w_p2r_fuse, s_p2r_fuse,
                                                   b_p2r_fuse, p2r_idx, out);
    k_p_out<<<NT / 256, 256, SMEM2>>>(w_r2p_fuse, s_r2p_fuse, b_r2p_fuse, out);
}

// round 10
// speedup vs baseline: 1.5968x; 1.5968x over previous
#include <cuda_runtime.h>
#include <cstdint>

#define BB   8
#define CC   64
#define NP   12800
#define NS   3200
#define KNN  16
#define HWD  19200
#define NOUT 22400
#define NT   25600          // BB*NS flattened

#define RSA  68             // A smem row stride (floats)
#define RSB  68             // B smem row stride (floats)
#define SM_A  0
#define SM_B1 (128 * RSA)                 // floats
#define SM_B2 (128 * RSA + 64 * RSB)
#define SMEMG ((128 * RSA + 2 * 64 * RSB) * 4)   // 69,632 B

// ---------------- scratch ----------------
__device__ __align__(16) float g_pT  [(size_t)BB * NP * CC];   // p point-major
__device__ __align__(16) float g_rgbT[(size_t)BB * HWD * CC];  // rgb point-major
__device__ __align__(16) float g_pemb[(size_t)NT * CC];        // p_emb0 point-major
__device__ __align__(16) float g_r2pg[(size_t)NT * CC];        // rgb gather+max point-major
__device__ __align__(16) float g_q   [(size_t)NT * CC];        // Wfuse_hi @ p2r point-major
__device__ __align__(16) float g_r2pp[(size_t)NT * CC];        // r2p_pre point-major

// ---------------- tf32 split helpers ----------------
__device__ __forceinline__ void split_tf32(float x, uint32_t& h, uint32_t& l) {
    h = __float_as_uint(x) & 0xFFFFE000u;
    float lf = x - __uint_as_float(h);
    asm("cvt.rna.tf32.f32 %0, %1;" : "=r"(l) : "f"(lf));
}

__device__ __forceinline__ void mma8(float c[4], const uint32_t a[4], const uint32_t b[2]) {
    asm volatile(
        "mma.sync.aligned.m16n8k8.row.col.f32.tf32.tf32.f32 "
        "{%0,%1,%2,%3}, {%4,%5,%6,%7}, {%8,%9}, {%0,%1,%2,%3};"
        : "+f"(c[0]), "+f"(c[1]), "+f"(c[2]), "+f"(c[3])
        : "r"(a[0]), "r"(a[1]), "r"(a[2]), "r"(a[3]), "r"(b[0]), "r"(b[1]));
}

// ---------------- transpose [B,64,N] -> [B,N,64] (known-good) ----------------
__device__ __forceinline__ void transpose_body(const float* __restrict__ src,
                                               float* __restrict__ dst, int N, int n0) {
    __shared__ __align__(16) float s[32][33];
    const int b = blockIdx.z, c0 = blockIdx.y * 32;
    const int tx = threadIdx.x, ty = threadIdx.y;
    const float* sp = src + ((size_t)b * CC + c0) * N + n0;
#pragma unroll
    for (int i = 0; i < 4; i++)
        s[ty + 8 * i][tx] = sp[(size_t)(ty + 8 * i) * N + tx];
    __syncthreads();
    float* dp = dst + ((size_t)b * N + n0) * CC + c0;
#pragma unroll
    for (int i = 0; i < 4; i++)
        dp[(size_t)(ty + 8 * i) * CC + tx] = s[tx][ty + 8 * i];
}
__global__ void __launch_bounds__(256, 2)
k_transpose_all(const float* __restrict__ p, const float* __restrict__ rgb) {
    if (blockIdx.x < NP / 32) transpose_body(p,   g_pT,   NP,  blockIdx.x * 32);
    else                      transpose_body(rgb, g_rgbT, HWD, (blockIdx.x - NP / 32) * 32);
}

// ---------------- gather + maxpool, point-major out (known-good) ----------------
__device__ __forceinline__ void gather_body(const float* __restrict__ srcT,
                                            const int* __restrict__ idx,
                                            float* __restrict__ dstT, int Nsrc, int bx) {
    const int wid = threadIdx.x >> 5, lane = threadIdx.x & 31;
    const int gid = bx * 8 + wid;
    const int b = gid / NS;
    const int* ip = idx + (size_t)gid * KNN;
    int id[KNN];
#pragma unroll
    for (int k = 0; k < KNN; k++) id[k] = __ldg(ip + k);
    float2 v[KNN];
#pragma unroll
    for (int k = 0; k < KNN; k++)
        v[k] = __ldg((const float2*)(srcT + ((size_t)b * Nsrc + id[k]) * CC) + lane);
    float2 acc = v[0];
#pragma unroll
    for (int k = 1; k < KNN; k++) {
        acc.x = fmaxf(acc.x, v[k].x);
        acc.y = fmaxf(acc.y, v[k].y);
    }
    ((float2*)(dstT + (size_t)gid * CC))[lane] = acc;
}
__global__ void __launch_bounds__(256, 2)
k_gather_all(const int* __restrict__ pool_idx, const int* __restrict__ r2p_idx) {
    const int half = NT / 8;
    if (blockIdx.x < half) gather_body(g_pT,   pool_idx, g_pemb, NP,  blockIdx.x);
    else                   gather_body(g_rgbT, r2p_idx,  g_r2pg, HWD, blockIdx.x - half);
}

// ---------------- staging ----------------
// A: 128 points x 64 c from point-major gmem, float4 coalesced
__device__ __forceinline__ void stage_A(float* Asm, const float* __restrict__ src, int t) {
#pragma unroll
    for (int i = 0; i < 8; i++) {
        int f4 = t + 256 * i;                 // < 2048
        int p = f4 >> 4, c4 = f4 & 15;
        float4 v = __ldg((const float4*)src + (size_t)p * 16 + c4);
        *(float4*)(Asm + p * RSA + 4 * c4) = v;
    }
}
// B: 64 o-rows x 64 c from weight gmem (row stride)
__device__ __forceinline__ void stage_B(float* Bsm, const float* __restrict__ w,
                                        int stride, int t) {
#pragma unroll
    for (int i = 0; i < 16; i++) {
        int f = t + 256 * i;                  // < 4096
        int o = f >> 6, c = f & 63;
        Bsm[o * RSB + c] = __ldg(w + (size_t)o * stride + c);
    }
}

// ---------------- warp MMA: acc[p 128][o 64] += Asm @ Bsm^T, tf32 3-pass ----------------
// warp wm = (wid&3)*32 (2 m16 tiles), wn = (wid>>2)*32 (4 n8 tiles)
__device__ __forceinline__ void warp_mma(const float* Asm, const float* Bsm,
                                         float acc[2][4][4], int lane, int wm, int wn) {
    const int r = lane >> 2, c = lane & 3;
#pragma unroll
    for (int ks = 0; ks < 8; ks++) {
        const int k0 = 8 * ks;
        uint32_t ah[2][4], al[2][4];
#pragma unroll
        for (int mt = 0; mt < 2; mt++) {
            const float* ab = Asm + (wm + 16 * mt + r) * RSA + k0 + c;
            split_tf32(ab[0],           ah[mt][0], al[mt][0]);
            split_tf32(ab[8 * RSA],     ah[mt][1], al[mt][1]);
            split_tf32(ab[4],           ah[mt][2], al[mt][2]);
            split_tf32(ab[8 * RSA + 4], ah[mt][3], al[mt][3]);
        }
        uint32_t bh[4][2], bl[4][2];
#pragma unroll
        for (int nt = 0; nt < 4; nt++) {
            const float* bb = Bsm + (wn + 8 * nt + r) * RSB + k0 + c;
            split_tf32(bb[0], bh[nt][0], bl[nt][0]);
            split_tf32(bb[4], bh[nt][1], bl[nt][1]);
        }
#pragma unroll
        for (int mt = 0; mt < 2; mt++)
#pragma unroll
            for (int nt = 0; nt < 4; nt++) mma8(acc[mt][nt], ah[mt], bh[nt]);
#pragma unroll
        for (int mt = 0; mt < 2; mt++)
#pragma unroll
            for (int nt = 0; nt < 4; nt++) mma8(acc[mt][nt], ah[mt], bl[nt]);
#pragma unroll
        for (int mt = 0; mt < 2; mt++)
#pragma unroll
            for (int nt = 0; nt < 4; nt++) mma8(acc[mt][nt], al[mt], bh[nt]);
    }
}

// ---------------- k_pre: y=0 p2r chain -> g_q ; y=1 r2p_pre -> g_r2pp ----------------
__global__ void __launch_bounds__(256, 2)
k_pre(const float* __restrict__ w_p2r_pre, const float* __restrict__ s_p2r_pre,
      const float* __restrict__ b_p2r_pre, const float* __restrict__ w_p2r_fuse,
      const float* __restrict__ w_r2p_pre, const float* __restrict__ s_r2p_pre,
      const float* __restrict__ b_r2p_pre) {
    extern __shared__ __align__(16) float sm[];
    float* Asm = sm + SM_A;
    float* Bs1 = sm + SM_B1;
    float* Bs2 = sm + SM_B2;
    const int t = threadIdx.x, lane = t & 31, wid = t >> 5;
    const int wm = (wid & 3) * 32, wn = (wid >> 2) * 32;
    const int r = lane >> 2, c = lane & 3;
    const int n0 = blockIdx.x * 128;
    const int r2p = blockIdx.y;

    const float* sA  = r2p ? g_r2pg : g_pemb;
    const float* wP  = r2p ? w_r2p_pre : w_p2r_pre;
    const float* sP  = r2p ? s_r2p_pre : s_p2r_pre;
    const float* bP  = r2p ? b_r2p_pre : b_p2r_pre;

    stage_A(Asm, sA + (size_t)n0 * CC, t);
    stage_B(Bs1, wP, 64, t);
    if (!r2p) stage_B(Bs2, w_p2r_fuse + 64, 128, t);
    __syncthreads();

    float acc[2][4][4] = {};
    warp_mma(Asm, Bs1, acc, lane, wm, wn);

    // relu(s*acc+b)
    float sv[4][2], bv[4][2];
#pragma unroll
    for (int nt = 0; nt < 4; nt++) {
        int o0 = wn + 8 * nt + 2 * c;
        sv[nt][0] = __ldg(sP + o0);     bv[nt][0] = __ldg(bP + o0);
        sv[nt][1] = __ldg(sP + o0 + 1); bv[nt][1] = __ldg(bP + o0 + 1);
    }
#pragma unroll
    for (int mt = 0; mt < 2; mt++)
#pragma unroll
        for (int nt = 0; nt < 4; nt++) {
            acc[mt][nt][0] = fmaxf(acc[mt][nt][0] * sv[nt][0] + bv[nt][0], 0.0f);
            acc[mt][nt][1] = fmaxf(acc[mt][nt][1] * sv[nt][1] + bv[nt][1], 0.0f);
            acc[mt][nt][2] = fmaxf(acc[mt][nt][2] * sv[nt][0] + bv[nt][0], 0.0f);
            acc[mt][nt][3] = fmaxf(acc[mt][nt][3] * sv[nt][1] + bv[nt][1], 0.0f);
        }

    if (r2p) {
        // store r2p_pre point-major
#pragma unroll
        for (int mt = 0; mt < 2; mt++)
#pragma unroll
            for (int nt = 0; nt < 4; nt++) {
                int p0 = wm + 16 * mt + r, o0 = wn + 8 * nt + 2 * c;
                *(float2*)(g_r2pp + (size_t)(n0 + p0) * CC + o0) =
                    make_float2(acc[mt][nt][0], acc[mt][nt][1]);
                *(float2*)(g_r2pp + (size_t)(n0 + p0 + 8) * CC + o0) =
                    make_float2(acc[mt][nt][2], acc[mt][nt][3]);
            }
    } else {
        // restage t into Asm, GEMM2, store q
        __syncthreads();
#pragma unroll
        for (int mt = 0; mt < 2; mt++)
#pragma unroll
            for (int nt = 0; nt < 4; nt++) {
                int p0 = wm + 16 * mt + r, o0 = wn + 8 * nt + 2 * c;
                Asm[(p0)     * RSA + o0]     = acc[mt][nt][0];
                Asm[(p0)     * RSA + o0 + 1] = acc[mt][nt][1];
                Asm[(p0 + 8) * RSA + o0]     = acc[mt][nt][2];
                Asm[(p0 + 8) * RSA + o0 + 1] = acc[mt][nt][3];
            }
        __syncthreads();

        float acc2[2][4][4] = {};
        warp_mma(Asm, Bs2, acc2, lane, wm, wn);
#pragma unroll
        for (int mt = 0; mt < 2; mt++)
#pragma unroll
            for (int nt = 0; nt < 4; nt++) {
                int p0 = wm + 16 * mt + r, o0 = wn + 8 * nt + 2 * c;
                *(float2*)(g_q + (size_t)(n0 + p0) * CC + o0) =
                    make_float2(acc2[mt][nt][0], acc2[mt][nt][1]);
                *(float2*)(g_q + (size_t)(n0 + p0 + 8) * CC + o0) =
                    make_float2(acc2[mt][nt][2], acc2[mt][nt][3]);
            }
    }
}

// ---------------- k_rgb_out: relu(s*(W_lo@rgb + q[p2r_idx]) + b) ----------------
__global__ void __launch_bounds__(256, 2)
k_rgb_out(const float* __restrict__ w_fuse, const float* __restrict__ s,
          const float* __restrict__ bias, const int* __restrict__ p2r_idx,
          float* __restrict__ out) {
    extern __shared__ __align__(16) float sm[];
    float* Asm = sm + SM_A;
    float* Bs1 = sm + SM_B1;
    const int t = threadIdx.x, lane = t & 31, wid = t >> 5;
    const int wm = (wid & 3) * 32, wn = (wid >> 2) * 32;
    const int r = lane >> 2, c = lane & 3;
    const int bI = blockIdx.y, n0 = blockIdx.x * 128;

    stage_A(Asm, g_rgbT + ((size_t)bI * HWD + n0) * CC, t);
    stage_B(Bs1, w_fuse, 128, t);
    __syncthreads();

    float acc[2][4][4] = {};
    warp_mma(Asm, Bs1, acc, lane, wm, wn);

    float sv[4][2], bv[4][2];
#pragma unroll
    for (int nt = 0; nt < 4; nt++) {
        int o0 = wn + 8 * nt + 2 * c;
        sv[nt][0] = __ldg(s + o0);     bv[nt][0] = __ldg(bias + o0);
        sv[nt][1] = __ldg(s + o0 + 1); bv[nt][1] = __ldg(bias + o0 + 1);
    }

    const int* ip = p2r_idx + (size_t)bI * HWD + n0;
    const float* qb = g_q + (size_t)bI * NS * CC;
#pragma unroll
    for (int mt = 0; mt < 2; mt++) {
        int p0 = wm + 16 * mt + r;
        int giA = __ldg(ip + p0);
        int giB = __ldg(ip + p0 + 8);
        const float* qA = qb + (size_t)giA * CC;
        const float* qB = qb + (size_t)giB * CC;
#pragma unroll
        for (int nt = 0; nt < 4; nt++) {
            int o0 = wn + 8 * nt + 2 * c;
            float2 qa = *(const float2*)(qA + o0);
            float2 qc = *(const float2*)(qB + o0);
            float v0 = fmaxf((acc[mt][nt][0] + qa.x) * sv[nt][0] + bv[nt][0], 0.0f);
            float v1 = fmaxf((acc[mt][nt][1] + qa.y) * sv[nt][1] + bv[nt][1], 0.0f);
            float v2 = fmaxf((acc[mt][nt][2] + qc.x) * sv[nt][0] + bv[nt][0], 0.0f);
            float v3 = fmaxf((acc[mt][nt][3] + qc.y) * sv[nt][1] + bv[nt][1], 0.0f);
            out[((size_t)(bI * CC + o0))     * NOUT + n0 + p0]     = v0;
            out[((size_t)(bI * CC + o0 + 1)) * NOUT + n0 + p0]     = v1;
            out[((size_t)(bI * CC + o0))     * NOUT + n0 + p0 + 8] = v2;
            out[((size_t)(bI * CC + o0 + 1)) * NOUT + n0 + p0 + 8] = v3;
        }
    }
}

// ---------------- k_p_out: relu(s*(Wf_lo@p_emb0 + Wf_hi@r2p_pre) + b) ----------------
__global__ void __launch_bounds__(256, 2)
k_p_out(const float* __restrict__ w_fuse, const float* __restrict__ s,
        const float* __restrict__ bias, float* __restrict__ out) {
    extern __shared__ __align__(16) float sm[];
    float* Asm = sm + SM_A;
    float* Bs1 = sm + SM_B1;
    float* Bs2 = sm + SM_B2;
    const int t = threadIdx.x, lane = t & 31, wid = t >> 5;
    const int wm = (wid & 3) * 32, wn = (wid >> 2) * 32;
    const int r = lane >> 2, c = lane & 3;
    const int n0 = blockIdx.x * 128;

    stage_A(Asm, g_pemb + (size_t)n0 * CC, t);
    stage_B(Bs1, w_fuse, 128, t);
    stage_B(Bs2, w_fuse + 64, 128, t);
    __syncthreads();

    float acc[2][4][4] = {};
    warp_mma(Asm, Bs1, acc, lane, wm, wn);

    __syncthreads();
    stage_A(Asm, g_r2pp + (size_t)n0 * CC, t);
    __syncthreads();
    warp_mma(Asm, Bs2, acc, lane, wm, wn);

    float sv[4][2], bv[4][2];
#pragma unroll
    for (int nt = 0; nt < 4; nt++) {
        int o0 = wn + 8 * nt + 2 * c;
        sv[nt][0] = __ldg(s + o0);     bv[nt][0] = __ldg(bias + o0);
        sv[nt][1] = __ldg(s + o0 + 1); bv[nt][1] = __ldg(bias + o0 + 1);
    }
#pragma unroll
    for (int mt = 0; mt < 2; mt++) {
        int p0 = wm + 16 * mt + r;
#pragma unroll
        for (int half = 0; half < 2; half++) {
            int ng = n0 + p0 + 8 * half;
            int bb = ng / NS, col = ng - bb * NS;
#pragma unroll
            for (int nt = 0; nt < 4; nt++) {
                int o0 = wn + 8 * nt + 2 * c;
                float v0 = fmaxf(acc[mt][nt][2 * half]     * sv[nt][0] + bv[nt][0], 0.0f);
                float v1 = fmaxf(acc[mt][nt][2 * half + 1] * sv[nt][1] + bv[nt][1], 0.0f);
                out[((size_t)(bb * CC + o0))     * NOUT + HWD + col] = v0;
                out[((size_t)(bb * CC + o0 + 1)) * NOUT + HWD + col] = v1;
            }
        }
    }
}

// ---------------- launch ----------------
extern "C" void kernel_launch(void* const* d_in, const int* in_sizes, int n_in,
                              void* d_out, int out_size) {
    const float* rgb_feat   = (const float*)d_in[0];
    const float* p_feat     = (const float*)d_in[1];
    const float* w_p2r_pre  = (const float*)d_in[2];
    const float* s_p2r_pre  = (const float*)d_in[3];
    const float* b_p2r_pre  = (const float*)d_in[4];
    const float* w_p2r_fuse = (const float*)d_in[5];
    const float* s_p2r_fuse = (const float*)d_in[6];
    const float* b_p2r_fuse = (const float*)d_in[7];
    const float* w_r2p_pre  = (const float*)d_in[8];
    const float* s_r2p_pre  = (const float*)d_in[9];
    const float* b_r2p_pre  = (const float*)d_in[10];
    const float* w_r2p_fuse = (const float*)d_in[11];
    const float* s_r2p_fuse = (const float*)d_in[12];
    const float* b_r2p_fuse = (const float*)d_in[13];
    const int*   pool_idx   = (const int*)d_in[14];
    const int*   p2r_idx    = (const int*)d_in[15];
    const int*   r2p_idx    = (const int*)d_in[16];
    float* out = (float*)d_out;

    cudaFuncSetAttribute(k_pre,     cudaFuncAttributeMaxDynamicSharedMemorySize, SMEMG);
    cudaFuncSetAttribute(k_rgb_out, cudaFuncAttributeMaxDynamicSharedMemorySize, SMEMG);
    cudaFuncSetAttribute(k_p_out,   cudaFuncAttributeMaxDynamicSharedMemorySize, SMEMG);

    k_transpose_all<<<dim3(NP / 32 + HWD / 32, 2, BB), dim3(32, 8)>>>(p_feat, rgb_feat);
    k_gather_all<<<2 * (NT / 8), 256>>>(pool_idx, r2p_idx);

    k_pre<<<dim3(NT / 128, 2), 256, SMEMG>>>(w_p2r_pre, s_p2r_pre, b_p2r_pre, w_p2r_fuse,
                                             w_r2p_pre, s_r2p_pre, b_r2p_pre);

    k_rgb_out<<<dim3(HWD / 128, BB), 256, SMEMG>>>(w_p2r_fuse, s_p2r_fuse, b_p2r_fuse,
                                                   p2r_idx, out);
    k_p_out<<<NT / 128, 256, SMEMG>>>(w_r2p_fuse, s_r2p_fuse, b_r2p_fuse, out);
}